// round 1
// baseline (speedup 1.0000x reference)
#include <cuda_runtime.h>
#include <cstdint>

#define S_ 1024
#define B_ 32
#define H_ 512
#define E_ 512
#define A_ 256

// ---------------- device scratch (static allocation; no cudaMalloc) -------------
__device__ float g_emb_att[(size_t)S_ * B_ * A_];   // [k*B+b][a]   33.5 MB
__device__ float g_q_att[(size_t)S_ * B_ * A_];     // [q*B+b][a]   33.5 MB
__device__ float g_wexp[(size_t)B_ * S_ * S_];      // [b][q][k]    134 MB (unnormalized exp scores)
__device__ float g_rowsum[S_ * B_];                 // [q*B+b]
__device__ float g_context[(size_t)S_ * B_ * E_];   // [q*B+b][e]   67 MB

__device__ __forceinline__ float tanh_fast(float x) {
    float y;
    asm("tanh.approx.f32 %0, %1;" : "=f"(y) : "f"(x));
    return y;
}

// ---------------- zero-fill scratch weights ------------------------------------
__global__ void __launch_bounds__(256) zero_wexp_kernel() {
    size_t i = (size_t)blockIdx.x * blockDim.x + threadIdx.x;
    float4 z = {0.f, 0.f, 0.f, 0.f};
    reinterpret_cast<float4*>(g_wexp)[i] = z;
}

// ---------------- generic C = A @ W^T (+bias) (+accum) -------------------------
// A: [M,K] row-major (optional row remap m>=32 -> m-32 for the q_att projection)
// W: [N,K] row-major.  C: [M,N] row-major.
#define GBM 128
#define GBN 64
#define GBK 16
__global__ void __launch_bounds__(256) gemm_awt_kernel(
    const float* __restrict__ A, const float* __restrict__ W,
    const float* __restrict__ bias1, const float* __restrict__ bias2,
    float* __restrict__ C, int M, int N, int K, int remap, int accum)
{
    __shared__ float As[GBK][GBM];
    __shared__ float Bs[GBK][GBN];
    int tid = threadIdx.x;
    int m0 = blockIdx.x * GBM;
    int n0 = blockIdx.y * GBN;
    int tx = tid & 15;   // 16 * 4 = 64 cols
    int ty = tid >> 4;   // 16 * 8 = 128 rows
    int ar = tid >> 2;          // 0..63
    int ac = (tid & 3) * 4;     // k quad
    float acc[8][4] = {};
    for (int k0 = 0; k0 < K; k0 += GBK) {
#pragma unroll
        for (int i = 0; i < 2; i++) {
            int gr = m0 + ar + i * 64;
            int sr = remap ? (gr >= 32 ? gr - 32 : gr) : gr;
            float4 av = *reinterpret_cast<const float4*>(&A[(size_t)sr * K + k0 + ac]);
            As[ac + 0][ar + i * 64] = av.x;
            As[ac + 1][ar + i * 64] = av.y;
            As[ac + 2][ar + i * 64] = av.z;
            As[ac + 3][ar + i * 64] = av.w;
        }
        {
            float4 wv = *reinterpret_cast<const float4*>(&W[(size_t)(n0 + ar) * K + k0 + ac]);
            Bs[ac + 0][ar] = wv.x;
            Bs[ac + 1][ar] = wv.y;
            Bs[ac + 2][ar] = wv.z;
            Bs[ac + 3][ar] = wv.w;
        }
        __syncthreads();
#pragma unroll
        for (int kk = 0; kk < GBK; kk++) {
            float a_frag[8], b_frag[4];
#pragma unroll
            for (int i = 0; i < 8; i++) a_frag[i] = As[kk][ty * 8 + i];
#pragma unroll
            for (int j = 0; j < 4; j++) b_frag[j] = Bs[kk][tx * 4 + j];
#pragma unroll
            for (int i = 0; i < 8; i++)
#pragma unroll
                for (int j = 0; j < 4; j++) acc[i][j] += a_frag[i] * b_frag[j];
        }
        __syncthreads();
    }
#pragma unroll
    for (int i = 0; i < 8; i++) {
        int m = m0 + ty * 8 + i;
#pragma unroll
        for (int j = 0; j < 4; j++) {
            int n = n0 + tx * 4 + j;
            float val = acc[i][j];
            if (bias1) val += bias1[n];
            if (bias2) val += bias2[n];
            size_t idx = (size_t)m * N + n;
            if (accum) val += C[idx];
            C[idx] = val;
        }
    }
}

// ---------------- scores: w~[b][q][k] = exp(v . tanh(qa+ea)), rowsums ----------
#define TQ 16
#define KC 64
#define QPAD 260
#define KPAD 68
#define SCORE_SMEM ((256 + TQ * QPAD + A_ * KPAD + TQ) * 4)

__global__ void __launch_bounds__(256) score_kernel(const float* __restrict__ v)
{
    extern __shared__ float sm[];
    float* v_s   = sm;                       // 256
    float* qa_s  = v_s + 256;                // TQ x QPAD
    float* ea_s  = qa_s + TQ * QPAD;         // A_ x KPAD  (transposed: [a][k])
    float* sum_s = ea_s + A_ * KPAD;         // TQ

    int tid = threadIdx.x;
    int q0 = blockIdx.x * TQ;
    int b = blockIdx.y;

    // load v
    if (tid < 64) {
        float4 vv = *reinterpret_cast<const float4*>(&v[tid * 4]);
        v_s[tid * 4 + 0] = vv.x; v_s[tid * 4 + 1] = vv.y;
        v_s[tid * 4 + 2] = vv.z; v_s[tid * 4 + 3] = vv.w;
    }
    // load qa tile: TQ x A_ (1024 float4s, 4 per thread)
#pragma unroll
    for (int i = 0; i < 4; i++) {
        int lin = tid + i * 256;           // 0..1023
        int q = lin >> 6;                  // /64
        int aq = lin & 63;
        float4 qv = *reinterpret_cast<const float4*>(
            &g_q_att[((size_t)(q0 + q) * B_ + b) * A_ + aq * 4]);
        float* dst = &qa_s[q * QPAD + aq * 4];
        dst[0] = qv.x; dst[1] = qv.y; dst[2] = qv.z; dst[3] = qv.w;
    }
    if (tid < TQ) sum_s[tid] = 0.f;
    __syncthreads();

    int q = tid >> 4;                 // 0..15
    int kq4 = (tid & 15) * 4;         // 0,4,...,60
    int qg = q0 + q;
    int Lq = max(1, qg - 1);
    const float* qrow = &qa_s[q * QPAD];
    size_t wbase = ((size_t)b * S_ + qg) * S_;

    int Lmax = max(1, q0 + TQ - 2);
    int kend = (Lmax + KC - 1) / KC * KC;    // <= S_
    float thread_sum = 0.f;

    for (int k0 = 0; k0 < kend; k0 += KC) {
        // load ea chunk (KC keys x A_), transposed into ea_s[a][k]
#pragma unroll
        for (int i = 0; i < 16; i++) {
            int lin = tid + i * 256;       // 0..4095
            int k = lin >> 6;              // 0..63
            int aq = lin & 63;
            float4 ev = *reinterpret_cast<const float4*>(
                &g_emb_att[((size_t)(k0 + k) * B_ + b) * A_ + aq * 4]);
            ea_s[(aq * 4 + 0) * KPAD + k] = ev.x;
            ea_s[(aq * 4 + 1) * KPAD + k] = ev.y;
            ea_s[(aq * 4 + 2) * KPAD + k] = ev.z;
            ea_s[(aq * 4 + 3) * KPAD + k] = ev.w;
        }
        __syncthreads();

        float a0 = 0.f, a1 = 0.f, a2 = 0.f, a3 = 0.f;
#pragma unroll 4
        for (int a = 0; a < A_; a++) {
            float qv = qrow[a];
            float vv = v_s[a];
            float4 ev = *reinterpret_cast<const float4*>(&ea_s[a * KPAD + kq4]);
            a0 += vv * tanh_fast(qv + ev.x);
            a1 += vv * tanh_fast(qv + ev.y);
            a2 += vv * tanh_fast(qv + ev.z);
            a3 += vv * tanh_fast(qv + ev.w);
        }

        int kk = k0 + kq4;
        float4 wv;
        wv.x = (kk + 0 < Lq) ? __expf(a0) : 0.f;
        wv.y = (kk + 1 < Lq) ? __expf(a1) : 0.f;
        wv.z = (kk + 2 < Lq) ? __expf(a2) : 0.f;
        wv.w = (kk + 3 < Lq) ? __expf(a3) : 0.f;
        *reinterpret_cast<float4*>(&g_wexp[wbase + kk]) = wv;
        thread_sum += wv.x + wv.y + wv.z + wv.w;
        __syncthreads();
    }

    atomicAdd(&sum_s[q], thread_sum);
    __syncthreads();
    if (tid < TQ) g_rowsum[(q0 + tid) * B_ + b] = sum_s[tid];
}

// ---------------- normalize + transpose (b,q,k) -> weights (q,k,b) -------------
__global__ void __launch_bounds__(256) norm_transpose_kernel(float* __restrict__ wout)
{
    __shared__ float tile[32][33];
    __shared__ float inv_s[32];
    int tid = threadIdx.x;
    int q = blockIdx.y;
    int k0 = blockIdx.x * 32;
    int tx = tid & 31;
    int ty = tid >> 5;   // 0..7
    if (tid < 32) inv_s[tid] = 1.f / g_rowsum[q * B_ + tid];
#pragma unroll
    for (int i = 0; i < 4; i++) {
        int bb = ty + i * 8;
        tile[bb][tx] = g_wexp[((size_t)bb * S_ + q) * S_ + k0 + tx];
    }
    __syncthreads();
#pragma unroll
    for (int i = 0; i < 4; i++) {
        int kk = ty + i * 8;
        wout[((size_t)q * S_ + k0 + kk) * B_ + tx] = tile[tx][kk] * inv_s[tx];
    }
}

// ---------------- context[q,b,e] = sum_k w[q,k,b] * emb[k,b,e] ------------------
__global__ void __launch_bounds__(256) context_kernel(const float* __restrict__ emb)
{
    __shared__ float As[GBK][GBM];
    __shared__ float Bs[GBK][GBN];
    __shared__ float scale_s[GBM];
    int tid = threadIdx.x;
    int m0 = blockIdx.x * GBM;     // q tile
    int n0 = blockIdx.y * GBN;     // e tile
    int b  = blockIdx.z;
    int tx = tid & 15;
    int ty = tid >> 4;
    int ar = tid >> 2;
    int ac = (tid & 3) * 4;
    const float* A = &g_wexp[(size_t)b * S_ * S_];
    float acc[8][4] = {};

    if (tid < GBM) scale_s[tid] = 1.f / g_rowsum[(m0 + tid) * B_ + b];

    int Lmax = max(1, m0 + GBM - 2);
    int Kr = min(S_, (Lmax + 15) & ~15);
    for (int k0 = 0; k0 < Kr; k0 += GBK) {
#pragma unroll
        for (int i = 0; i < 2; i++) {
            int gr = m0 + ar + i * 64;
            float4 av = *reinterpret_cast<const float4*>(&A[(size_t)gr * S_ + k0 + ac]);
            As[ac + 0][ar + i * 64] = av.x;
            As[ac + 1][ar + i * 64] = av.y;
            As[ac + 2][ar + i * 64] = av.z;
            As[ac + 3][ar + i * 64] = av.w;
        }
        {
            int kk = tid >> 4;          // 0..15
            int nn = (tid & 15) * 4;
            float4 bv = *reinterpret_cast<const float4*>(
                &emb[((size_t)(k0 + kk) * B_ + b) * E_ + n0 + nn]);
            Bs[kk][nn + 0] = bv.x; Bs[kk][nn + 1] = bv.y;
            Bs[kk][nn + 2] = bv.z; Bs[kk][nn + 3] = bv.w;
        }
        __syncthreads();
#pragma unroll
        for (int kk = 0; kk < GBK; kk++) {
            float a_frag[8], b_frag[4];
#pragma unroll
            for (int i = 0; i < 8; i++) a_frag[i] = As[kk][ty * 8 + i];
#pragma unroll
            for (int j = 0; j < 4; j++) b_frag[j] = Bs[kk][tx * 4 + j];
#pragma unroll
            for (int i = 0; i < 8; i++)
#pragma unroll
                for (int j = 0; j < 4; j++) acc[i][j] += a_frag[i] * b_frag[j];
        }
        __syncthreads();
    }
#pragma unroll
    for (int i = 0; i < 8; i++) {
        int m = m0 + ty * 8 + i;
        float sc = scale_s[ty * 8 + i];
#pragma unroll
        for (int j = 0; j < 4; j++) {
            int n = n0 + tx * 4 + j;
            g_context[((size_t)m * B_ + b) * E_ + n] = acc[i][j] * sc;
        }
    }
}

// ---------------- launch --------------------------------------------------------
extern "C" void kernel_launch(void* const* d_in, const int* in_sizes, int n_in,
                              void* d_out, int out_size)
{
    const float* outs  = (const float*)d_in[0];
    const float* emb   = (const float*)d_in[1];
    const float* W_enc = (const float*)d_in[2];
    const float* b_enc = (const float*)d_in[3];
    const float* W_dec = (const float*)d_in[4];
    const float* b_dec = (const float*)d_in[5];
    const float* v     = (const float*)d_in[6];
    const float* W_h2h = (const float*)d_in[7];
    const float* b_h2h = (const float*)d_in[8];
    const float* W_e2h = (const float*)d_in[9];
    const float* b_e2h = (const float*)d_in[10];
    float* out = (float*)d_out;

    float *p_emb_att, *p_q_att, *p_context;
    cudaGetSymbolAddress((void**)&p_emb_att, g_emb_att);
    cudaGetSymbolAddress((void**)&p_q_att, g_q_att);
    cudaGetSymbolAddress((void**)&p_context, g_context);

    cudaFuncSetAttribute(score_kernel, cudaFuncAttributeMaxDynamicSharedMemorySize, SCORE_SMEM);

    const size_t OUT1 = (size_t)S_ * B_ * H_;          // 16,777,216 (output)
    const size_t WSZ  = (size_t)S_ * S_ * B_;          // 33,554,432 (weights)
    bool hasW = ((size_t)out_size >= OUT1 + WSZ);

    // 1. zero the scratch score buffer (covers the triangular masked region)
    zero_wexp_kernel<<<(int)(WSZ / 4 / 256), 256>>>();

    // 2. projections: emb_att = emb @ W_enc^T + b_enc ; q_att = outs[t] @ W_dec^T + b_dec
    gemm_awt_kernel<<<dim3((S_ * B_) / GBM, A_ / GBN), 256>>>(
        emb, W_enc, b_enc, nullptr, p_emb_att, S_ * B_, A_, E_, 0, 0);
    gemm_awt_kernel<<<dim3((S_ * B_) / GBM, A_ / GBN), 256>>>(
        outs, W_dec, b_dec, nullptr, p_q_att, S_ * B_, A_, H_, 1, 0);

    // 3. scores + exp + rowsums
    score_kernel<<<dim3(S_ / TQ, B_), 256, SCORE_SMEM>>>(v);

    // 4. normalized weights output (q,k,b)
    if (hasW)
        norm_transpose_kernel<<<dim3(S_ / 32, S_), 256>>>(out + OUT1);

    // 5. context
    context_kernel<<<dim3(S_ / GBM, E_ / GBN, B_), 256>>>(emb);

    // 6. output = outs @ W_h2h^T + b_h2h + b_e2h, then += context @ W_e2h^T
    gemm_awt_kernel<<<dim3((S_ * B_) / GBM, H_ / GBN), 256>>>(
        outs, W_h2h, b_h2h, b_e2h, out, S_ * B_, H_, H_, 0, 0);
    gemm_awt_kernel<<<dim3((S_ * B_) / GBM, H_ / GBN), 256>>>(
        p_context, W_e2h, nullptr, nullptr, out, S_ * B_, H_, E_, 0, 1);
}

// round 2
// speedup vs baseline: 1.4765x; 1.4765x over previous
#include <cuda_runtime.h>
#include <cstdint>

#define S_ 1024
#define B_ 32
#define H_ 512
#define E_ 512
#define A_ 256

// ---------------- device scratch (static allocation; no cudaMalloc) -------------
__device__ float g_emb_att[(size_t)S_ * B_ * A_];   // [k*B+b][a]
__device__ float g_q_att[(size_t)S_ * B_ * A_];     // [q*B+b][a]
__device__ float g_wexp[(size_t)B_ * S_ * S_];      // [b][q][k] unnormalized exp scores
__device__ float g_rowsum[S_ * B_];                 // [q*B+b]
__device__ float g_context[(size_t)S_ * B_ * E_];   // [q*B+b][e]

__device__ __forceinline__ float tanh_fast(float x) {
    float y;
    asm("tanh.approx.f32 %0, %1;" : "=f"(y) : "f"(x));
    return y;
}

__device__ __forceinline__ uint32_t f2tf32(float x) {
    uint32_t u;
    asm("cvt.rna.tf32.f32 %0, %1;" : "=r"(u) : "f"(x));
    return u;
}

// ---------------- zero-fill scratch weights ------------------------------------
__global__ void __launch_bounds__(256) zero_wexp_kernel() {
    size_t i = (size_t)blockIdx.x * blockDim.x + threadIdx.x;
    float4 z = {0.f, 0.f, 0.f, 0.f};
    reinterpret_cast<float4*>(g_wexp)[i] = z;
}

// ---------------- tf32 tensor-core GEMM ----------------------------------------
// MODE 0: C[M,N] = A[M,K] @ W[N,K]^T (+bias1+bias2) (+accum), all row-major fp32.
//         optional row remap (m>=32 -> m-32) on A.
// MODE 1: context: per-batch b (blockIdx.z):
//         C[(m*B+b)*E+n] = (1/rowsum[m*B+b]) * sum_k wexp[b][m][k] * emb[(k*B+b)*E+n]
#define BM 128
#define BN 128
#define BKK 16
#define ASTR 20     // A smem row stride (floats) — banks 20r+c bijective
#define BSTR 136    // B smem row stride (floats) — banks 8k+n bijective

template<int MODE>
__global__ void __launch_bounds__(256) mma_gemm(
    const float* __restrict__ A, const float* __restrict__ Bm,
    const float* __restrict__ bias1, const float* __restrict__ bias2,
    float* __restrict__ C, int M, int N, int K, int remap, int accum)
{
    __shared__ uint32_t As[2][BM * ASTR];
    __shared__ uint32_t Bs[2][BKK * BSTR];

    int tid = threadIdx.x;
    int m0 = blockIdx.x * BM;
    int n0 = blockIdx.y * BN;
    int b  = blockIdx.z;
    const float* Ap = (MODE == 1) ? (A + (size_t)b * S_ * S_) : A;

    int wid = tid >> 5, lane = tid & 31;
    int wm = (wid >> 2) * 64;     // warp m offset (0 / 64)
    int wn = (wid & 3) * 32;      // warp n offset
    int lr = lane >> 2;           // 0..7
    int lc = lane & 3;            // 0..3

    int a_row = tid >> 2;         // 0..63
    int a_c4  = tid & 3;          // k float4 index

    float acc[4][4][4];
#pragma unroll
    for (int i = 0; i < 4; i++)
#pragma unroll
        for (int j = 0; j < 4; j++)
#pragma unroll
            for (int r = 0; r < 4; r++) acc[i][j][r] = 0.f;

    int Kr = K;
    if (MODE == 1) {
        int Lmax = max(1, m0 + BM - 2);
        Kr = min(K, (Lmax + 15) & ~15);
    }
    int niter = Kr / BKK;

    float4 a_st[2], b_st[2];

    auto gload = [&](int k0) {
#pragma unroll
        for (int j = 0; j < 2; j++) {
            int gr = m0 + a_row + j * 64;
            int sr = (MODE == 0 && remap) ? (gr >= 32 ? gr - 32 : gr) : gr;
            a_st[j] = *reinterpret_cast<const float4*>(&Ap[(size_t)sr * K + k0 + a_c4 * 4]);
        }
        if (MODE == 0) {
#pragma unroll
            for (int j = 0; j < 2; j++) {
                int n = a_row + j * 64;
                b_st[j] = *reinterpret_cast<const float4*>(&Bm[(size_t)(n0 + n) * K + k0 + a_c4 * 4]);
            }
        } else {
#pragma unroll
            for (int j = 0; j < 2; j++) {
                int i = tid + j * 256;
                int kk = i >> 5, c = i & 31;
                b_st[j] = *reinterpret_cast<const float4*>(
                    &Bm[((size_t)(k0 + kk) * B_ + b) * E_ + n0 + c * 4]);
            }
        }
    };

    auto sstore = [&](int buf) {
#pragma unroll
        for (int j = 0; j < 2; j++) {
            int row = a_row + j * 64;
            uint32_t* p = &As[buf][row * ASTR + a_c4 * 4];
            p[0] = f2tf32(a_st[j].x); p[1] = f2tf32(a_st[j].y);
            p[2] = f2tf32(a_st[j].z); p[3] = f2tf32(a_st[j].w);
        }
        if (MODE == 0) {
#pragma unroll
            for (int j = 0; j < 2; j++) {
                int n = a_row + j * 64;
                Bs[buf][(a_c4 * 4 + 0) * BSTR + n] = f2tf32(b_st[j].x);
                Bs[buf][(a_c4 * 4 + 1) * BSTR + n] = f2tf32(b_st[j].y);
                Bs[buf][(a_c4 * 4 + 2) * BSTR + n] = f2tf32(b_st[j].z);
                Bs[buf][(a_c4 * 4 + 3) * BSTR + n] = f2tf32(b_st[j].w);
            }
        } else {
#pragma unroll
            for (int j = 0; j < 2; j++) {
                int i = tid + j * 256;
                int kk = i >> 5, c = i & 31;
                uint32_t* p = &Bs[buf][kk * BSTR + c * 4];
                p[0] = f2tf32(b_st[j].x); p[1] = f2tf32(b_st[j].y);
                p[2] = f2tf32(b_st[j].z); p[3] = f2tf32(b_st[j].w);
            }
        }
    };

    // prologue: tile 0
    gload(0);
    sstore(0);
    __syncthreads();

    int buf = 0;
    for (int it = 0; it < niter; it++) {
        if (it + 1 < niter) gload((it + 1) * BKK);

        // compute tile `buf`: two k8 steps
#pragma unroll
        for (int s = 0; s < 2; s++) {
            int k8 = s * 8;
            uint32_t af[4][4], bf[4][2];
#pragma unroll
            for (int mt = 0; mt < 4; mt++) {
                int mb = wm + mt * 16 + lr;
                af[mt][0] = As[buf][(mb)     * ASTR + k8 + lc];
                af[mt][1] = As[buf][(mb + 8) * ASTR + k8 + lc];
                af[mt][2] = As[buf][(mb)     * ASTR + k8 + 4 + lc];
                af[mt][3] = As[buf][(mb + 8) * ASTR + k8 + 4 + lc];
            }
#pragma unroll
            for (int nt = 0; nt < 4; nt++) {
                int nb = wn + nt * 8 + lr;
                bf[nt][0] = Bs[buf][(k8 + lc)     * BSTR + nb];
                bf[nt][1] = Bs[buf][(k8 + 4 + lc) * BSTR + nb];
            }
#pragma unroll
            for (int mt = 0; mt < 4; mt++)
#pragma unroll
                for (int nt = 0; nt < 4; nt++) {
                    float* d = acc[mt][nt];
                    asm volatile(
                        "mma.sync.aligned.m16n8k8.row.col.f32.tf32.tf32.f32 "
                        "{%0,%1,%2,%3},{%4,%5,%6,%7},{%8,%9},{%0,%1,%2,%3};"
                        : "+f"(d[0]), "+f"(d[1]), "+f"(d[2]), "+f"(d[3])
                        : "r"(af[mt][0]), "r"(af[mt][1]), "r"(af[mt][2]), "r"(af[mt][3]),
                          "r"(bf[nt][0]), "r"(bf[nt][1]));
                }
        }

        if (it + 1 < niter) {
            sstore(buf ^ 1);
            __syncthreads();
            buf ^= 1;
        }
    }

    // epilogue
#pragma unroll
    for (int mt = 0; mt < 4; mt++) {
        int mA = m0 + wm + mt * 16 + lr;      // rows mA and mA+8
        float sc0 = 1.f, sc1 = 1.f;
        if (MODE == 1) {
            sc0 = 1.f / g_rowsum[mA * B_ + b];
            sc1 = 1.f / g_rowsum[(mA + 8) * B_ + b];
        }
#pragma unroll
        for (int nt = 0; nt < 4; nt++) {
            int n = n0 + wn + nt * 8 + lc * 2;
            float* d = acc[mt][nt];
            if (MODE == 0) {
                float add0 = 0.f, add1 = 0.f;
                if (bias1) { add0 += bias1[n]; add1 += bias1[n + 1]; }
                if (bias2) { add0 += bias2[n]; add1 += bias2[n + 1]; }
                size_t i0 = (size_t)mA * N + n;
                size_t i1 = (size_t)(mA + 8) * N + n;
                float2 v0 = {d[0] + add0, d[1] + add1};
                float2 v1 = {d[2] + add0, d[3] + add1};
                if (accum) {
                    float2 o0 = *reinterpret_cast<float2*>(&C[i0]);
                    float2 o1 = *reinterpret_cast<float2*>(&C[i1]);
                    v0.x += o0.x; v0.y += o0.y;
                    v1.x += o1.x; v1.y += o1.y;
                }
                *reinterpret_cast<float2*>(&C[i0]) = v0;
                *reinterpret_cast<float2*>(&C[i1]) = v1;
            } else {
                size_t i0 = ((size_t)mA * B_ + b) * E_ + n;
                size_t i1 = ((size_t)(mA + 8) * B_ + b) * E_ + n;
                float2 v0 = {d[0] * sc0, d[1] * sc0};
                float2 v1 = {d[2] * sc1, d[3] * sc1};
                *reinterpret_cast<float2*>(&C[i0]) = v0;
                *reinterpret_cast<float2*>(&C[i1]) = v1;
            }
        }
    }
}

// ---------------- scores: w~[b][q][k] = exp(v . tanh(qa+ea)), rowsums ----------
#define TQ 16
#define KC 64
#define QPAD 260
#define KPAD 68
#define SCORE_SMEM ((256 + TQ * QPAD + A_ * KPAD + TQ) * 4)

__global__ void __launch_bounds__(256) score_kernel(const float* __restrict__ v)
{
    extern __shared__ float sm[];
    float* v_s   = sm;                       // 256
    float* qa_s  = v_s + 256;                // TQ x QPAD
    float* ea_s  = qa_s + TQ * QPAD;         // A_ x KPAD  (transposed: [a][k])
    float* sum_s = ea_s + A_ * KPAD;         // TQ

    int tid = threadIdx.x;
    int q0 = blockIdx.x * TQ;
    int b = blockIdx.y;

    if (tid < 64) {
        float4 vv = *reinterpret_cast<const float4*>(&v[tid * 4]);
        v_s[tid * 4 + 0] = vv.x; v_s[tid * 4 + 1] = vv.y;
        v_s[tid * 4 + 2] = vv.z; v_s[tid * 4 + 3] = vv.w;
    }
#pragma unroll
    for (int i = 0; i < 4; i++) {
        int lin = tid + i * 256;
        int q = lin >> 6;
        int aq = lin & 63;
        float4 qv = *reinterpret_cast<const float4*>(
            &g_q_att[((size_t)(q0 + q) * B_ + b) * A_ + aq * 4]);
        float* dst = &qa_s[q * QPAD + aq * 4];
        dst[0] = qv.x; dst[1] = qv.y; dst[2] = qv.z; dst[3] = qv.w;
    }
    if (tid < TQ) sum_s[tid] = 0.f;
    __syncthreads();

    int q = tid >> 4;
    int kq4 = (tid & 15) * 4;
    int qg = q0 + q;
    int Lq = max(1, qg - 1);
    const float* qrow = &qa_s[q * QPAD];
    size_t wbase = ((size_t)b * S_ + qg) * S_;

    int Lmax = max(1, q0 + TQ - 2);
    int kend = (Lmax + KC - 1) / KC * KC;
    float thread_sum = 0.f;

    for (int k0 = 0; k0 < kend; k0 += KC) {
#pragma unroll
        for (int i = 0; i < 16; i++) {
            int lin = tid + i * 256;
            int k = lin >> 6;
            int aq = lin & 63;
            float4 ev = *reinterpret_cast<const float4*>(
                &g_emb_att[((size_t)(k0 + k) * B_ + b) * A_ + aq * 4]);
            ea_s[(aq * 4 + 0) * KPAD + k] = ev.x;
            ea_s[(aq * 4 + 1) * KPAD + k] = ev.y;
            ea_s[(aq * 4 + 2) * KPAD + k] = ev.z;
            ea_s[(aq * 4 + 3) * KPAD + k] = ev.w;
        }
        __syncthreads();

        float a0 = 0.f, a1 = 0.f, a2 = 0.f, a3 = 0.f;
#pragma unroll 4
        for (int a = 0; a < A_; a++) {
            float qv = qrow[a];
            float vv = v_s[a];
            float4 ev = *reinterpret_cast<const float4*>(&ea_s[a * KPAD + kq4]);
            a0 += vv * tanh_fast(qv + ev.x);
            a1 += vv * tanh_fast(qv + ev.y);
            a2 += vv * tanh_fast(qv + ev.z);
            a3 += vv * tanh_fast(qv + ev.w);
        }

        int kk = k0 + kq4;
        float4 wv;
        wv.x = (kk + 0 < Lq) ? __expf(a0) : 0.f;
        wv.y = (kk + 1 < Lq) ? __expf(a1) : 0.f;
        wv.z = (kk + 2 < Lq) ? __expf(a2) : 0.f;
        wv.w = (kk + 3 < Lq) ? __expf(a3) : 0.f;
        *reinterpret_cast<float4*>(&g_wexp[wbase + kk]) = wv;
        thread_sum += wv.x + wv.y + wv.z + wv.w;
        __syncthreads();
    }

    atomicAdd(&sum_s[q], thread_sum);
    __syncthreads();
    if (tid < TQ) g_rowsum[(q0 + tid) * B_ + b] = sum_s[tid];
}

// ---------------- normalize + transpose (b,q,k) -> weights (q,k,b) -------------
__global__ void __launch_bounds__(256) norm_transpose_kernel(float* __restrict__ wout)
{
    __shared__ float tile[32][33];
    __shared__ float inv_s[32];
    int tid = threadIdx.x;
    int q = blockIdx.y;
    int k0 = blockIdx.x * 32;
    int tx = tid & 31;
    int ty = tid >> 5;
    if (tid < 32) inv_s[tid] = 1.f / g_rowsum[q * B_ + tid];
#pragma unroll
    for (int i = 0; i < 4; i++) {
        int bb = ty + i * 8;
        tile[bb][tx] = g_wexp[((size_t)bb * S_ + q) * S_ + k0 + tx];
    }
    __syncthreads();
#pragma unroll
    for (int i = 0; i < 4; i++) {
        int kk = ty + i * 8;
        wout[((size_t)q * S_ + k0 + kk) * B_ + tx] = tile[tx][kk] * inv_s[tx];
    }
}

// ---------------- launch --------------------------------------------------------
extern "C" void kernel_launch(void* const* d_in, const int* in_sizes, int n_in,
                              void* d_out, int out_size)
{
    const float* outs  = (const float*)d_in[0];
    const float* emb   = (const float*)d_in[1];
    const float* W_enc = (const float*)d_in[2];
    const float* b_enc = (const float*)d_in[3];
    const float* W_dec = (const float*)d_in[4];
    const float* b_dec = (const float*)d_in[5];
    const float* v     = (const float*)d_in[6];
    const float* W_h2h = (const float*)d_in[7];
    const float* b_h2h = (const float*)d_in[8];
    const float* W_e2h = (const float*)d_in[9];
    const float* b_e2h = (const float*)d_in[10];
    float* out = (float*)d_out;

    float *p_emb_att, *p_q_att, *p_context, *p_wexp;
    cudaGetSymbolAddress((void**)&p_emb_att, g_emb_att);
    cudaGetSymbolAddress((void**)&p_q_att, g_q_att);
    cudaGetSymbolAddress((void**)&p_context, g_context);
    cudaGetSymbolAddress((void**)&p_wexp, g_wexp);

    cudaFuncSetAttribute(score_kernel, cudaFuncAttributeMaxDynamicSharedMemorySize, SCORE_SMEM);

    const size_t OUT1 = (size_t)S_ * B_ * H_;
    const size_t WSZ  = (size_t)S_ * S_ * B_;
    bool hasW = ((size_t)out_size >= OUT1 + WSZ);

    // 1. zero the scratch score buffer (covers the triangular masked region)
    zero_wexp_kernel<<<(int)(WSZ / 4 / 256), 256>>>();

    // 2. projections (tf32 mma): emb_att, q_att
    mma_gemm<0><<<dim3((S_ * B_) / BM, A_ / BN), 256>>>(
        emb, W_enc, b_enc, nullptr, p_emb_att, S_ * B_, A_, E_, 0, 0);
    mma_gemm<0><<<dim3((S_ * B_) / BM, A_ / BN), 256>>>(
        outs, W_dec, b_dec, nullptr, p_q_att, S_ * B_, A_, H_, 1, 0);

    // 3. scores + exp + rowsums
    score_kernel<<<dim3(S_ / TQ, B_), 256, SCORE_SMEM>>>(v);

    // 4. normalized weights output (q,k,b)
    if (hasW)
        norm_transpose_kernel<<<dim3(S_ / 32, S_), 256>>>(out + OUT1);

    // 5. context (tf32 mma, triangular K, fused 1/rowsum scaling)
    mma_gemm<1><<<dim3(S_ / BM, E_ / BN, B_), 256>>>(
        p_wexp, emb, nullptr, nullptr, p_context, S_, E_, S_, 0, 0);

    // 6. output = outs @ W_h2h^T + b_h2h + b_e2h, then += context @ W_e2h^T
    mma_gemm<0><<<dim3((S_ * B_) / BM, H_ / BN), 256>>>(
        outs, W_h2h, b_h2h, b_e2h, out, S_ * B_, H_, H_, 0, 0);
    mma_gemm<0><<<dim3((S_ * B_) / BM, H_ / BN), 256>>>(
        p_context, W_e2h, nullptr, nullptr, out, S_ * B_, H_, E_, 0, 1);
}

// round 3
// speedup vs baseline: 1.4885x; 1.0081x over previous
#include <cuda_runtime.h>
#include <cuda_fp16.h>
#include <cstdint>

#define S_ 1024
#define B_ 32
#define H_ 512
#define E_ 512
#define A_ 256

// ---------------- device scratch (static allocation; no cudaMalloc) -------------
__device__ float g_emb_att[(size_t)S_ * B_ * A_];   // [k*B+b][a]
__device__ float g_q_att[(size_t)S_ * B_ * A_];     // [q*B+b][a]
__device__ float g_wexp[(size_t)B_ * S_ * S_];      // [b][q][k] unnormalized exp scores
__device__ float g_rowsum[S_ * B_];                 // [q*B+b]
__device__ float g_context[(size_t)S_ * B_ * E_];   // [q*B+b][e]

__device__ __forceinline__ uint32_t f2tf32(float x) {
    uint32_t u;
    asm("cvt.rna.tf32.f32 %0, %1;" : "=r"(u) : "f"(x));
    return u;
}
__device__ __forceinline__ uint32_t tf32_of_bits(uint32_t b) {
    return f2tf32(__uint_as_float(b));
}
__device__ __forceinline__ void cp_async16(uint32_t saddr, const void* g) {
    asm volatile("cp.async.cg.shared.global [%0], [%1], 16;\n" :: "r"(saddr), "l"(g));
}
#define CP_COMMIT() asm volatile("cp.async.commit_group;\n" ::: "memory")
#define CP_WAIT2()  asm volatile("cp.async.wait_group 2;\n" ::: "memory")

// ---------------- zero-fill scratch weights ------------------------------------
__global__ void __launch_bounds__(256) zero_wexp_kernel() {
    size_t i = (size_t)blockIdx.x * blockDim.x + threadIdx.x;
    float4 z = {0.f, 0.f, 0.f, 0.f};
    reinterpret_cast<float4*>(g_wexp)[i] = z;
}

// ---------------- tf32 tensor-core GEMM, 4-stage cp.async ----------------------
// MODE 0: C[M,N] = A[M,K] @ W[N,K]^T (+bias1+bias2) (+accum), row-major fp32.
//         optional row remap (m>=32 -> m-32) on A.
// MODE 1: context per batch b: C[(m*B+b)*E+n] =
//         (1/rowsum[m*B+b]) * sum_k wexp[b][m][k] * emb[(k*B+b)*E+n]
#define BM 128
#define BN 128
#define BKK 16
#define STAGES 4
#define ASTR 20      // [m][k] stride (words): banks 20r+c bijective for r<8,c<4
#define BSTRN 20     // MODE0 [n][k] stride
#define BSTRK 136    // MODE1 [k][n] stride: banks 8k+n bijective

#define ASZ   (BM * ASTR)
#define B0SZ  (BN * BSTRN)
#define B1SZ  (BKK * BSTRK)

template<int MODE>
__global__ void __launch_bounds__(256, 2) mma_gemm(
    const float* __restrict__ A, const float* __restrict__ Bm,
    const float* __restrict__ bias1, const float* __restrict__ bias2,
    float* __restrict__ C, int M, int N, int K, int remap, int accum)
{
    extern __shared__ uint32_t sh[];
    uint32_t* As = sh;                       // STAGES * ASZ
    uint32_t* Bs = sh + STAGES * ASZ;        // STAGES * (B0SZ or B1SZ)
    const int BSZ = (MODE == 0) ? B0SZ : B1SZ;

    int tid = threadIdx.x;
    int m0 = blockIdx.x * BM;
    int n0 = blockIdx.y * BN;
    int b  = blockIdx.z;
    const float* Ap = (MODE == 1) ? (A + (size_t)b * S_ * S_) : A;

    int wid = tid >> 5, lane = tid & 31;
    int wm = (wid >> 2) * 64;
    int wn = (wid & 3) * 32;
    int lr = lane >> 2;
    int lc = lane & 3;

    int Kr = K;
    if (MODE == 1) {
        int Lmax = max(1, m0 + BM - 2);
        Kr = min(K, (Lmax + 15) & ~15);
    }
    int niter = Kr / BKK;

    auto copy_stage = [&](int s, int k0) {
        uint32_t* Ad = As + s * ASZ;
        uint32_t* Bd = Bs + s * BSZ;
#pragma unroll
        for (int j = 0; j < 2; j++) {
            int cc = tid + j * 256;          // 0..511
            int row = cc >> 2;
            int kq = (cc & 3) * 4;
            int gr = m0 + row;
            int sr = (MODE == 0 && remap) ? (gr >= 32 ? gr - 32 : gr) : gr;
            cp_async16((uint32_t)__cvta_generic_to_shared(&Ad[row * ASTR + kq]),
                       &Ap[(size_t)sr * K + k0 + kq]);
        }
        if (MODE == 0) {
#pragma unroll
            for (int j = 0; j < 2; j++) {
                int cc = tid + j * 256;
                int row = cc >> 2;
                int kq = (cc & 3) * 4;
                cp_async16((uint32_t)__cvta_generic_to_shared(&Bd[row * BSTRN + kq]),
                           &Bm[(size_t)(n0 + row) * K + k0 + kq]);
            }
        } else {
#pragma unroll
            for (int j = 0; j < 2; j++) {
                int cc = tid + j * 256;
                int kk = cc >> 5;
                int nc = (cc & 31) * 4;
                cp_async16((uint32_t)__cvta_generic_to_shared(&Bd[kk * BSTRK + nc]),
                           &Bm[((size_t)(k0 + kk) * B_ + b) * E_ + n0 + nc]);
            }
        }
    };

    float acc[4][4][4];
#pragma unroll
    for (int i = 0; i < 4; i++)
#pragma unroll
        for (int j = 0; j < 4; j++)
#pragma unroll
            for (int r = 0; r < 4; r++) acc[i][j][r] = 0.f;

    // prologue: 3 stages in flight
#pragma unroll
    for (int s = 0; s < STAGES - 1; s++) {
        if (s < niter) copy_stage(s, s * BKK);
        CP_COMMIT();
    }

    for (int it = 0; it < niter; it++) {
        CP_WAIT2();
        __syncthreads();

        if (it + STAGES - 1 < niter)
            copy_stage((it + STAGES - 1) % STAGES, (it + STAGES - 1) * BKK);
        CP_COMMIT();

        uint32_t* Asb = As + (it % STAGES) * ASZ;
        uint32_t* Bsb = Bs + (it % STAGES) * BSZ;

#pragma unroll
        for (int s = 0; s < 2; s++) {
            int k8 = s * 8;
            uint32_t af[4][4], bf[4][2];
#pragma unroll
            for (int mt = 0; mt < 4; mt++) {
                int mb = wm + mt * 16 + lr;
                af[mt][0] = tf32_of_bits(Asb[(mb)     * ASTR + k8 + lc]);
                af[mt][1] = tf32_of_bits(Asb[(mb + 8) * ASTR + k8 + lc]);
                af[mt][2] = tf32_of_bits(Asb[(mb)     * ASTR + k8 + 4 + lc]);
                af[mt][3] = tf32_of_bits(Asb[(mb + 8) * ASTR + k8 + 4 + lc]);
            }
#pragma unroll
            for (int nt = 0; nt < 4; nt++) {
                int nb = wn + nt * 8 + lr;
                if (MODE == 0) {
                    bf[nt][0] = tf32_of_bits(Bsb[nb * BSTRN + k8 + lc]);
                    bf[nt][1] = tf32_of_bits(Bsb[nb * BSTRN + k8 + 4 + lc]);
                } else {
                    bf[nt][0] = tf32_of_bits(Bsb[(k8 + lc)     * BSTRK + nb]);
                    bf[nt][1] = tf32_of_bits(Bsb[(k8 + 4 + lc) * BSTRK + nb]);
                }
            }
#pragma unroll
            for (int mt = 0; mt < 4; mt++)
#pragma unroll
                for (int nt = 0; nt < 4; nt++) {
                    float* d = acc[mt][nt];
                    asm volatile(
                        "mma.sync.aligned.m16n8k8.row.col.f32.tf32.tf32.f32 "
                        "{%0,%1,%2,%3},{%4,%5,%6,%7},{%8,%9},{%0,%1,%2,%3};"
                        : "+f"(d[0]), "+f"(d[1]), "+f"(d[2]), "+f"(d[3])
                        : "r"(af[mt][0]), "r"(af[mt][1]), "r"(af[mt][2]), "r"(af[mt][3]),
                          "r"(bf[nt][0]), "r"(bf[nt][1]));
                }
        }
        __syncthreads();
    }

    // epilogue
#pragma unroll
    for (int mt = 0; mt < 4; mt++) {
        int mA = m0 + wm + mt * 16 + lr;
        float sc0 = 1.f, sc1 = 1.f;
        if (MODE == 1) {
            sc0 = 1.f / g_rowsum[mA * B_ + b];
            sc1 = 1.f / g_rowsum[(mA + 8) * B_ + b];
        }
#pragma unroll
        for (int nt = 0; nt < 4; nt++) {
            int n = n0 + wn + nt * 8 + lc * 2;
            float* d = acc[mt][nt];
            if (MODE == 0) {
                float add0 = 0.f, add1 = 0.f;
                if (bias1) { add0 += bias1[n]; add1 += bias1[n + 1]; }
                if (bias2) { add0 += bias2[n]; add1 += bias2[n + 1]; }
                size_t i0 = (size_t)mA * N + n;
                size_t i1 = (size_t)(mA + 8) * N + n;
                float2 v0 = {d[0] + add0, d[1] + add1};
                float2 v1 = {d[2] + add0, d[3] + add1};
                if (accum) {
                    float2 o0 = *reinterpret_cast<float2*>(&C[i0]);
                    float2 o1 = *reinterpret_cast<float2*>(&C[i1]);
                    v0.x += o0.x; v0.y += o0.y;
                    v1.x += o1.x; v1.y += o1.y;
                }
                *reinterpret_cast<float2*>(&C[i0]) = v0;
                *reinterpret_cast<float2*>(&C[i1]) = v1;
            } else {
                size_t i0 = ((size_t)mA * B_ + b) * E_ + n;
                size_t i1 = ((size_t)(mA + 8) * B_ + b) * E_ + n;
                float2 v0 = {d[0] * sc0, d[1] * sc0};
                float2 v1 = {d[2] * sc1, d[3] * sc1};
                *reinterpret_cast<float2*>(&C[i0]) = v0;
                *reinterpret_cast<float2*>(&C[i1]) = v1;
            }
        }
    }
}

// ---------------- scores: w~[b][q][k] = exp(v . tanh(qa+ea)), rowsums ----------
#define TQ 16
#define KC 64
#define QPAD 260
#define KPAD 68
#define SCORE_SMEM ((256 + TQ * QPAD + A_ * KPAD + TQ) * 4)

__global__ void __launch_bounds__(256) score_kernel(const float* __restrict__ v)
{
    extern __shared__ float sm[];
    float* v_s   = sm;
    float* qa_s  = v_s + 256;                // TQ x QPAD
    float* ea_s  = qa_s + TQ * QPAD;         // A_ x KPAD (transposed [a][k])
    float* sum_s = ea_s + A_ * KPAD;         // TQ

    int tid = threadIdx.x;
    int q0 = blockIdx.x * TQ;
    int b = blockIdx.y;

    if (tid < 64) {
        float4 vv = *reinterpret_cast<const float4*>(&v[tid * 4]);
        v_s[tid * 4 + 0] = vv.x; v_s[tid * 4 + 1] = vv.y;
        v_s[tid * 4 + 2] = vv.z; v_s[tid * 4 + 3] = vv.w;
    }
#pragma unroll
    for (int i = 0; i < 4; i++) {
        int lin = tid + i * 256;
        int q = lin >> 6;
        int aq = lin & 63;
        float4 qv = *reinterpret_cast<const float4*>(
            &g_q_att[((size_t)(q0 + q) * B_ + b) * A_ + aq * 4]);
        float* dst = &qa_s[q * QPAD + aq * 4];
        dst[0] = qv.x; dst[1] = qv.y; dst[2] = qv.z; dst[3] = qv.w;
    }
    if (tid < TQ) sum_s[tid] = 0.f;
    __syncthreads();

    int q = tid >> 4;
    int kq4 = (tid & 15) * 4;
    int qg = q0 + q;
    int Lq = max(1, qg - 1);
    const float* qrow = &qa_s[q * QPAD];
    size_t wbase = ((size_t)b * S_ + qg) * S_;

    int Lmax = max(1, q0 + TQ - 2);
    int kend = (Lmax + KC - 1) / KC * KC;
    float thread_sum = 0.f;

    for (int k0 = 0; k0 < kend; k0 += KC) {
#pragma unroll
        for (int i = 0; i < 16; i++) {
            int lin = tid + i * 256;
            int k = lin >> 6;
            int aq = lin & 63;
            float4 ev = *reinterpret_cast<const float4*>(
                &g_emb_att[((size_t)(k0 + k) * B_ + b) * A_ + aq * 4]);
            ea_s[(aq * 4 + 0) * KPAD + k] = ev.x;
            ea_s[(aq * 4 + 1) * KPAD + k] = ev.y;
            ea_s[(aq * 4 + 2) * KPAD + k] = ev.z;
            ea_s[(aq * 4 + 3) * KPAD + k] = ev.w;
        }
        __syncthreads();

        float a0 = 0.f, a1 = 0.f, a2 = 0.f, a3 = 0.f;
#pragma unroll 4
        for (int a = 0; a < A_; a++) {
            float qv = qrow[a];
            float vv = v_s[a];
            float4 ev = *reinterpret_cast<const float4*>(&ea_s[a * KPAD + kq4]);
            // f16x2 tanh: 2 results per MUFU op
            half2 h01 = __floats2half2_rn(qv + ev.x, qv + ev.y);
            half2 h23 = __floats2half2_rn(qv + ev.z, qv + ev.w);
            asm("tanh.approx.f16x2 %0, %0;" : "+r"(*reinterpret_cast<uint32_t*>(&h01)));
            asm("tanh.approx.f16x2 %0, %0;" : "+r"(*reinterpret_cast<uint32_t*>(&h23)));
            float2 f01 = __half22float2(h01);
            float2 f23 = __half22float2(h23);
            a0 += vv * f01.x;
            a1 += vv * f01.y;
            a2 += vv * f23.x;
            a3 += vv * f23.y;
        }

        int kk = k0 + kq4;
        float4 wv;
        wv.x = (kk + 0 < Lq) ? __expf(a0) : 0.f;
        wv.y = (kk + 1 < Lq) ? __expf(a1) : 0.f;
        wv.z = (kk + 2 < Lq) ? __expf(a2) : 0.f;
        wv.w = (kk + 3 < Lq) ? __expf(a3) : 0.f;
        *reinterpret_cast<float4*>(&g_wexp[wbase + kk]) = wv;
        thread_sum += wv.x + wv.y + wv.z + wv.w;
        __syncthreads();
    }

    atomicAdd(&sum_s[q], thread_sum);
    __syncthreads();
    if (tid < TQ) g_rowsum[(q0 + tid) * B_ + b] = sum_s[tid];
}

// ---------------- normalize + transpose (b,q,k) -> weights (q,k,b) -------------
__global__ void __launch_bounds__(256) norm_transpose_kernel(float* __restrict__ wout)
{
    __shared__ float tile[32][33];
    __shared__ float inv_s[32];
    int tid = threadIdx.x;
    int q = blockIdx.y;
    int k0 = blockIdx.x * 32;
    int tx = tid & 31;
    int ty = tid >> 5;
    if (tid < 32) inv_s[tid] = 1.f / g_rowsum[q * B_ + tid];
#pragma unroll
    for (int i = 0; i < 4; i++) {
        int bb = ty + i * 8;
        tile[bb][tx] = g_wexp[((size_t)bb * S_ + q) * S_ + k0 + tx];
    }
    __syncthreads();
#pragma unroll
    for (int i = 0; i < 4; i++) {
        int kk = ty + i * 8;
        wout[((size_t)q * S_ + k0 + kk) * B_ + tx] = tile[tx][kk] * inv_s[tx];
    }
}

// ---------------- launch --------------------------------------------------------
extern "C" void kernel_launch(void* const* d_in, const int* in_sizes, int n_in,
                              void* d_out, int out_size)
{
    const float* outs  = (const float*)d_in[0];
    const float* emb   = (const float*)d_in[1];
    const float* W_enc = (const float*)d_in[2];
    const float* b_enc = (const float*)d_in[3];
    const float* W_dec = (const float*)d_in[4];
    const float* b_dec = (const float*)d_in[5];
    const float* v     = (const float*)d_in[6];
    const float* W_h2h = (const float*)d_in[7];
    const float* b_h2h = (const float*)d_in[8];
    const float* W_e2h = (const float*)d_in[9];
    const float* b_e2h = (const float*)d_in[10];
    float* out = (float*)d_out;

    float *p_emb_att, *p_q_att, *p_context, *p_wexp;
    cudaGetSymbolAddress((void**)&p_emb_att, g_emb_att);
    cudaGetSymbolAddress((void**)&p_q_att, g_q_att);
    cudaGetSymbolAddress((void**)&p_context, g_context);
    cudaGetSymbolAddress((void**)&p_wexp, g_wexp);

    const int SMEM0 = STAGES * (ASZ + B0SZ) * 4;   // mode 0
    const int SMEM1 = STAGES * (ASZ + B1SZ) * 4;   // mode 1
    cudaFuncSetAttribute(mma_gemm<0>, cudaFuncAttributeMaxDynamicSharedMemorySize, SMEM0);
    cudaFuncSetAttribute(mma_gemm<1>, cudaFuncAttributeMaxDynamicSharedMemorySize, SMEM1);
    cudaFuncSetAttribute(score_kernel, cudaFuncAttributeMaxDynamicSharedMemorySize, SCORE_SMEM);

    const size_t OUT1 = (size_t)S_ * B_ * H_;
    const size_t WSZ  = (size_t)S_ * S_ * B_;
    bool hasW = ((size_t)out_size >= OUT1 + WSZ);

    // 1. zero the scratch score buffer
    zero_wexp_kernel<<<(int)(WSZ / 4 / 256), 256>>>();

    // 2. projections (tf32 mma): emb_att, q_att
    mma_gemm<0><<<dim3((S_ * B_) / BM, A_ / BN), 256, SMEM0>>>(
        emb, W_enc, b_enc, nullptr, p_emb_att, S_ * B_, A_, E_, 0, 0);
    mma_gemm<0><<<dim3((S_ * B_) / BM, A_ / BN), 256, SMEM0>>>(
        outs, W_dec, b_dec, nullptr, p_q_att, S_ * B_, A_, H_, 1, 0);

    // 3. scores + exp + rowsums
    score_kernel<<<dim3(S_ / TQ, B_), 256, SCORE_SMEM>>>(v);

    // 4. normalized weights output (q,k,b)
    if (hasW)
        norm_transpose_kernel<<<dim3(S_ / 32, S_), 256>>>(out + OUT1);

    // 5. context (tf32 mma, triangular K, fused 1/rowsum scaling)
    mma_gemm<1><<<dim3(S_ / BM, E_ / BN, B_), 256, SMEM1>>>(
        p_wexp, emb, nullptr, nullptr, p_context, S_, E_, S_, 0, 0);

    // 6. output = outs @ W_h2h^T + b_h2h + b_e2h, then += context @ W_e2h^T
    mma_gemm<0><<<dim3((S_ * B_) / BM, H_ / BN), 256, SMEM0>>>(
        outs, W_h2h, b_h2h, b_e2h, out, S_ * B_, H_, H_, 0, 0);
    mma_gemm<0><<<dim3((S_ * B_) / BM, H_ / BN), 256, SMEM0>>>(
        p_context, W_e2h, nullptr, nullptr, out, S_ * B_, H_, E_, 0, 1);
}

// round 4
// speedup vs baseline: 2.2166x; 1.4891x over previous
#include <cuda_runtime.h>
#include <cuda_fp16.h>
#include <cstdint>

#define S_ 1024
#define B_ 32
#define H_ 512
#define E_ 512
#define A_ 256

// ---------------- device scratch ------------------------------------------------
__device__ __half g_outs_h[(size_t)S_ * B_ * H_];
__device__ __half g_emb_h[(size_t)S_ * B_ * E_];
__device__ __half g_Wenc_h[A_ * E_];
__device__ __half g_Wdec_h[A_ * H_];
__device__ __half g_Wh2h_h[H_ * H_];
__device__ __half g_We2h_h[H_ * E_];
__device__ __half g_emb_att_h[(size_t)S_ * B_ * A_];   // [k*B+b][a]
__device__ __half g_q_att_h[(size_t)S_ * B_ * A_];     // [q*B+b][a]
__device__ __half g_wexp_h[(size_t)B_ * S_ * S_];      // [b][q][k]
__device__ __half g_context_h[(size_t)S_ * B_ * E_];   // [q*B+b][e]
__device__ float  g_rowsum[S_ * B_];                   // [q*B+b]

// ---------------- small helpers -------------------------------------------------
__device__ __forceinline__ __half2 u2h2(uint32_t u) { return *reinterpret_cast<__half2*>(&u); }
__device__ __forceinline__ uint32_t h22u(__half2 h) { return *reinterpret_cast<uint32_t*>(&h); }
__device__ __forceinline__ __half2 tanh2(__half2 x) {
    uint32_t u = h22u(x);
    asm("tanh.approx.f16x2 %0, %0;" : "+r"(u));
    return u2h2(u);
}
__device__ __forceinline__ void cpa16(uint32_t s, const void* g) {
    asm volatile("cp.async.cg.shared.global [%0], [%1], 16;" :: "r"(s), "l"(g));
}
#define CP_COMMIT() asm volatile("cp.async.commit_group;" ::: "memory")
#define CP_WAIT2()  asm volatile("cp.async.wait_group 2;" ::: "memory")

__device__ __forceinline__ void ldsm4(uint32_t& r0, uint32_t& r1, uint32_t& r2, uint32_t& r3, uint32_t a) {
    asm volatile("ldmatrix.sync.aligned.m8n8.x4.shared.b16 {%0,%1,%2,%3},[%4];"
                 : "=r"(r0), "=r"(r1), "=r"(r2), "=r"(r3) : "r"(a));
}
__device__ __forceinline__ void ldsm4t(uint32_t& r0, uint32_t& r1, uint32_t& r2, uint32_t& r3, uint32_t a) {
    asm volatile("ldmatrix.sync.aligned.m8n8.x4.trans.shared.b16 {%0,%1,%2,%3},[%4];"
                 : "=r"(r0), "=r"(r1), "=r"(r2), "=r"(r3) : "r"(a));
}
__device__ __forceinline__ void mma16816(float* d, const uint32_t* a, const uint32_t* b) {
    asm volatile("mma.sync.aligned.m16n8k16.row.col.f32.f16.f16.f32 "
                 "{%0,%1,%2,%3},{%4,%5,%6,%7},{%8,%9},{%0,%1,%2,%3};"
                 : "+f"(d[0]), "+f"(d[1]), "+f"(d[2]), "+f"(d[3])
                 : "r"(a[0]), "r"(a[1]), "r"(a[2]), "r"(a[3]), "r"(b[0]), "r"(b[1]));
}

// ---------------- convert fp32 -> fp16 ------------------------------------------
__global__ void __launch_bounds__(256) f2h_kernel(const float* __restrict__ src,
                                                  __half* __restrict__ dst, int n8) {
    int i = blockIdx.x * blockDim.x + threadIdx.x;
    if (i < n8) {
        float4 f0 = reinterpret_cast<const float4*>(src)[i * 2];
        float4 f1 = reinterpret_cast<const float4*>(src)[i * 2 + 1];
        __half2 h[4] = { __floats2half2_rn(f0.x, f0.y), __floats2half2_rn(f0.z, f0.w),
                         __floats2half2_rn(f1.x, f1.y), __floats2half2_rn(f1.z, f1.w) };
        reinterpret_cast<uint4*>(dst)[i] = *reinterpret_cast<uint4*>(h);
    }
}

// ---------------- zero wexp -----------------------------------------------------
__global__ void __launch_bounds__(256) zero_wexp_kernel() {
    size_t i = (size_t)blockIdx.x * blockDim.x + threadIdx.x;
    uint4 z = {0u, 0u, 0u, 0u};
    reinterpret_cast<uint4*>(g_wexp_h)[i] = z;
}

// ---------------- fp16 tensor-core GEMM, 4-stage cp.async -----------------------
// MODE 0: C(half)[M,N] = A@W^T + bias1 ; W is [N][K] half; optional row remap.
// MODE 1: context per b: Chalf[(m*B+b)*E+n] = (1/rowsum)*sum_k wexp_h[b][m][k]*emb_h[(k*B+b)*E+n]
// MODE 2: Cfloat[M,N] = A@W1^T + A2@W2^T + bias1 + bias2 (K=1024 split at 512)
#define BM 128
#define BN 128
#define BK 16
#define STG 4
#define ASTR 24        // halves per A/B0 row (48B, conflict-free for LDSM)
#define B1STR 136      // halves per B1 row (272B)
#define ASZ  (BM * ASTR)     // 3072 halves
#define B0SZ (BN * ASTR)     // 3072
#define B1SZ (BK * B1STR)    // 2176

template<int MODE>
__global__ void __launch_bounds__(256, 2) hgemm(
    const __half* __restrict__ A, const __half* __restrict__ Bm,
    const __half* __restrict__ A2, const __half* __restrict__ Bm2,
    const float* __restrict__ bias1, const float* __restrict__ bias2,
    void* __restrict__ Cv, int M, int N, int K, int remap)
{
    extern __shared__ __half sh[];
    const int BSZ = (MODE == 1) ? B1SZ : B0SZ;
    __half* Asm = sh;
    __half* Bsm = sh + STG * ASZ;

    int tid = threadIdx.x;
    int m0 = blockIdx.x * BM, n0 = blockIdx.y * BN, b = blockIdx.z;
    const __half* Ap = (MODE == 1) ? (A + (size_t)b * S_ * S_) : A;

    int wid = tid >> 5, lane = tid & 31;
    int wm = (wid >> 2) * 64, wn = (wid & 3) * 32;

    int Kr = K;
    if (MODE == 1) { int Lmax = max(1, m0 + BM - 2); Kr = min(K, (Lmax + 15) & ~15); }
    int niter = Kr / BK;

    int arow = tid >> 1, ak8 = (tid & 1) * 8;
    int b1row = tid >> 4, b1n8 = (tid & 15) * 8;

    auto copy_stage = [&](int s, int k0) {
        __half* Ad = Asm + s * ASZ;
        __half* Bd = Bsm + s * BSZ;
        const __half* Asrc = Ap; const __half* Bsrc = Bm; int kk = k0;
        if (MODE == 2 && k0 >= 512) { Asrc = A2; Bsrc = Bm2; kk = k0 - 512; }
        {
            int gr = m0 + arow;
            int sr = (MODE == 0 && remap) ? (gr >= B_ ? gr - B_ : gr) : gr;
            int KA = (MODE == 1) ? S_ : ((MODE == 2) ? 512 : K);
            cpa16((uint32_t)__cvta_generic_to_shared(Ad + arow * ASTR + ak8),
                  Asrc + (size_t)sr * KA + kk + ak8);
        }
        if (MODE == 1) {
            cpa16((uint32_t)__cvta_generic_to_shared(Bd + b1row * B1STR + b1n8),
                  Bsrc + ((size_t)(k0 + b1row) * B_ + b) * E_ + n0 + b1n8);
        } else {
            int KB = (MODE == 2) ? 512 : K;
            cpa16((uint32_t)__cvta_generic_to_shared(Bd + arow * ASTR + ak8),
                  Bsrc + (size_t)(n0 + arow) * KB + kk + ak8);
        }
    };

    // fragment smem byte addresses (stage 0)
    uint32_t a_off[4], b_off[2];
    {
        int r = lane & 15, koff = (lane >> 4) * 8;
#pragma unroll
        for (int mt = 0; mt < 4; mt++) {
            int row = wm + mt * 16 + r;
            a_off[mt] = (uint32_t)__cvta_generic_to_shared(Asm + row * ASTR + koff);
        }
        if (MODE == 1) {
            int k = ((lane >> 3) & 1) * 8 + (lane & 7);
#pragma unroll
            for (int p = 0; p < 2; p++) {
                int n = wn + p * 16 + (lane >> 4) * 8;
                b_off[p] = (uint32_t)__cvta_generic_to_shared(Bsm + k * B1STR + n);
            }
        } else {
            int koffb = ((lane >> 3) & 1) * 8;
            int nb = (lane >> 4) * 8 + (lane & 7);
#pragma unroll
            for (int p = 0; p < 2; p++) {
                int n = wn + p * 16 + nb;
                b_off[p] = (uint32_t)__cvta_generic_to_shared(Bsm + n * ASTR + koffb);
            }
        }
    }

    float acc[4][4][4];
#pragma unroll
    for (int i = 0; i < 4; i++)
#pragma unroll
        for (int j = 0; j < 4; j++)
#pragma unroll
            for (int r = 0; r < 4; r++) acc[i][j][r] = 0.f;

#pragma unroll
    for (int s = 0; s < STG - 1; s++) {
        if (s < niter) copy_stage(s, s * BK);
        CP_COMMIT();
    }

    for (int it = 0; it < niter; it++) {
        CP_WAIT2();
        __syncthreads();
        if (it + STG - 1 < niter) copy_stage((it + STG - 1) % STG, (it + STG - 1) * BK);
        CP_COMMIT();

        uint32_t ab = (uint32_t)((it % STG) * ASZ * 2);
        uint32_t bb = (uint32_t)((it % STG) * BSZ * 2);

        uint32_t af[4][4], bf[2][4];
#pragma unroll
        for (int mt = 0; mt < 4; mt++)
            ldsm4(af[mt][0], af[mt][1], af[mt][2], af[mt][3], a_off[mt] + ab);
#pragma unroll
        for (int p = 0; p < 2; p++) {
            if (MODE == 1) ldsm4t(bf[p][0], bf[p][1], bf[p][2], bf[p][3], b_off[p] + bb);
            else           ldsm4 (bf[p][0], bf[p][1], bf[p][2], bf[p][3], b_off[p] + bb);
        }
#pragma unroll
        for (int mt = 0; mt < 4; mt++)
#pragma unroll
            for (int nt = 0; nt < 4; nt++)
                mma16816(acc[mt][nt], af[mt], &bf[nt >> 1][(nt & 1) * 2]);
        __syncthreads();
    }

    // epilogue
    int lr = lane >> 2, lc = lane & 3;
#pragma unroll
    for (int mt = 0; mt < 4; mt++) {
        int mA = m0 + wm + mt * 16 + lr;
        float sc0 = 1.f, sc1 = 1.f;
        if (MODE == 1) {
            sc0 = 1.f / g_rowsum[mA * B_ + b];
            sc1 = 1.f / g_rowsum[(mA + 8) * B_ + b];
        }
#pragma unroll
        for (int nt = 0; nt < 4; nt++) {
            int n = n0 + wn + nt * 8 + lc * 2;
            float* d = acc[mt][nt];
            if (MODE == 0) {
                float a0 = bias1 ? bias1[n] : 0.f, a1 = bias1 ? bias1[n + 1] : 0.f;
                __half* C = (__half*)Cv;
                *reinterpret_cast<__half2*>(&C[(size_t)mA * N + n]) =
                    __floats2half2_rn(d[0] + a0, d[1] + a1);
                *reinterpret_cast<__half2*>(&C[(size_t)(mA + 8) * N + n]) =
                    __floats2half2_rn(d[2] + a0, d[3] + a1);
            } else if (MODE == 1) {
                __half* C = (__half*)Cv;
                *reinterpret_cast<__half2*>(&C[((size_t)mA * B_ + b) * E_ + n]) =
                    __floats2half2_rn(d[0] * sc0, d[1] * sc0);
                *reinterpret_cast<__half2*>(&C[((size_t)(mA + 8) * B_ + b) * E_ + n]) =
                    __floats2half2_rn(d[2] * sc1, d[3] * sc1);
            } else {
                float a0 = bias1[n] + bias2[n], a1 = bias1[n + 1] + bias2[n + 1];
                float* C = (float*)Cv;
                float2 v0 = {d[0] + a0, d[1] + a1};
                float2 v1 = {d[2] + a0, d[3] + a1};
                *reinterpret_cast<float2*>(&C[(size_t)mA * N + n]) = v0;
                *reinterpret_cast<float2*>(&C[(size_t)(mA + 8) * N + n]) = v1;
            }
        }
    }
}

// ---------------- scores: half2 tanh, MUFU-bound --------------------------------
// block: 256 threads = 16 q x 16 key-groups (8 keys each); chunks of 128 keys.
#define SQ 16
#define SCORE_W (16384 + 4096 + 256 + 16)
#define SCORE_SMEM (SCORE_W * 4)

__global__ void __launch_bounds__(256) score_kernel(const float* __restrict__ v)
{
    extern __shared__ uint32_t sw[];
    uint32_t* ea2 = sw;                 // [256 a][64 k2] half2
    uint32_t* qa2 = sw + 16384;         // [16 q][256 a] dup-half2
    float* vs   = (float*)(sw + 16384 + 4096);   // [256]
    float* sums = vs + 256;             // [16]

    int tid = threadIdx.x;
    int q0 = blockIdx.x * SQ, b = blockIdx.y;
    int q = tid >> 4, kq = tid & 15;
    int qg = q0 + q;
    int Lq = max(1, qg - 1);

    vs[tid] = v[tid];
    if (tid < SQ) sums[tid] = 0.f;
#pragma unroll
    for (int it = 0; it < 2; it++) {
        int lin = tid + it * 256;
        int qq = lin >> 5, a8 = lin & 31;
        uint4 u = *reinterpret_cast<const uint4*>(
            g_q_att_h + ((size_t)(q0 + qq) * B_ + b) * A_ + a8 * 8);
        __half h[8]; *reinterpret_cast<uint4*>(h) = u;
#pragma unroll
        for (int i = 0; i < 8; i++) {
            __half2 d = __half2half2(h[i]);
            qa2[qq * 256 + a8 * 8 + i] = h22u(d);
        }
    }

    int Lmax = max(1, q0 + SQ - 2);
    size_t wrow = ((size_t)b * S_ + qg) * S_;

    for (int k0 = 0; k0 < Lmax; k0 += 128) {
        __syncthreads();
        // fill ea2: keys k0..k0+127 paired into half2, transposed to [a][k2]
#pragma unroll
        for (int it = 0; it < 8; it++) {
            int lin = tid + it * 256;
            int k2 = lin & 63, a8 = lin >> 6;
            const __half* p = g_emb_att_h + ((size_t)(k0 + 2 * k2) * B_ + b) * A_ + a8 * 8;
            uint4 u0 = *reinterpret_cast<const uint4*>(p);
            uint4 u1 = *reinterpret_cast<const uint4*>(p + (size_t)B_ * A_);
            __half h0[8], h1[8];
            *reinterpret_cast<uint4*>(h0) = u0;
            *reinterpret_cast<uint4*>(h1) = u1;
#pragma unroll
            for (int i = 0; i < 8; i++) {
                __half2 d = __halves2half2(h0[i], h1[i]);
                ea2[(a8 * 8 + i) * 64 + k2] = h22u(d);
            }
        }
        __syncthreads();

        float acc[8] = {0.f, 0.f, 0.f, 0.f, 0.f, 0.f, 0.f, 0.f};
#pragma unroll 4
        for (int a = 0; a < A_; a++) {
            uint4 e = *reinterpret_cast<uint4*>(&ea2[a * 64 + kq * 4]);
            __half2 qh = u2h2(qa2[q * 256 + a]);
            float vf = vs[a];
            float2 f0 = __half22float2(tanh2(__hadd2(qh, u2h2(e.x))));
            float2 f1 = __half22float2(tanh2(__hadd2(qh, u2h2(e.y))));
            float2 f2 = __half22float2(tanh2(__hadd2(qh, u2h2(e.z))));
            float2 f3 = __half22float2(tanh2(__hadd2(qh, u2h2(e.w))));
            acc[0] = fmaf(vf, f0.x, acc[0]); acc[1] = fmaf(vf, f0.y, acc[1]);
            acc[2] = fmaf(vf, f1.x, acc[2]); acc[3] = fmaf(vf, f1.y, acc[3]);
            acc[4] = fmaf(vf, f2.x, acc[4]); acc[5] = fmaf(vf, f2.y, acc[5]);
            acc[6] = fmaf(vf, f3.x, acc[6]); acc[7] = fmaf(vf, f3.y, acc[7]);
        }

        int kb = k0 + kq * 8;
        float sl = 0.f;
        __half2 o[4];
#pragma unroll
        for (int j = 0; j < 4; j++) {
            float w0 = (kb + 2 * j     < Lq) ? __expf(acc[2 * j])     : 0.f;
            float w1 = (kb + 2 * j + 1 < Lq) ? __expf(acc[2 * j + 1]) : 0.f;
            sl += w0 + w1;
            o[j] = __floats2half2_rn(w0, w1);
        }
        *reinterpret_cast<uint4*>(&g_wexp_h[wrow + kb]) = *reinterpret_cast<uint4*>(o);
        atomicAdd(&sums[q], sl);
    }
    __syncthreads();
    if (tid < SQ) g_rowsum[(q0 + tid) * B_ + b] = sums[tid];
}

// ---------------- normalize + transpose (b,q,k) -> weights (q,k,b) -------------
__global__ void __launch_bounds__(256) norm_transpose_kernel(float* __restrict__ wout)
{
    __shared__ float tile[32][33];
    __shared__ float inv_s[32];
    int tid = threadIdx.x;
    int q = blockIdx.y;
    int k0 = blockIdx.x * 32;
    int tx = tid & 31;
    int ty = tid >> 5;
    if (tid < 32) inv_s[tid] = 1.f / g_rowsum[q * B_ + tid];
#pragma unroll
    for (int i = 0; i < 4; i++) {
        int bb = ty + i * 8;
        tile[bb][tx] = __half2float(g_wexp_h[((size_t)bb * S_ + q) * S_ + k0 + tx]);
    }
    __syncthreads();
#pragma unroll
    for (int i = 0; i < 4; i++) {
        int kk = ty + i * 8;
        wout[((size_t)q * S_ + k0 + kk) * B_ + tx] = tile[tx][kk] * inv_s[tx];
    }
}

// ---------------- launch --------------------------------------------------------
extern "C" void kernel_launch(void* const* d_in, const int* in_sizes, int n_in,
                              void* d_out, int out_size)
{
    const float* outs  = (const float*)d_in[0];
    const float* emb   = (const float*)d_in[1];
    const float* W_enc = (const float*)d_in[2];
    const float* b_enc = (const float*)d_in[3];
    const float* W_dec = (const float*)d_in[4];
    const float* b_dec = (const float*)d_in[5];
    const float* v     = (const float*)d_in[6];
    const float* W_h2h = (const float*)d_in[7];
    const float* b_h2h = (const float*)d_in[8];
    const float* W_e2h = (const float*)d_in[9];
    const float* b_e2h = (const float*)d_in[10];
    float* out = (float*)d_out;

    __half *p_outs_h, *p_emb_h, *p_Wenc, *p_Wdec, *p_Wh2h, *p_We2h;
    __half *p_emb_att, *p_q_att, *p_wexp, *p_ctx;
    cudaGetSymbolAddress((void**)&p_outs_h, g_outs_h);
    cudaGetSymbolAddress((void**)&p_emb_h, g_emb_h);
    cudaGetSymbolAddress((void**)&p_Wenc, g_Wenc_h);
    cudaGetSymbolAddress((void**)&p_Wdec, g_Wdec_h);
    cudaGetSymbolAddress((void**)&p_Wh2h, g_Wh2h_h);
    cudaGetSymbolAddress((void**)&p_We2h, g_We2h_h);
    cudaGetSymbolAddress((void**)&p_emb_att, g_emb_att_h);
    cudaGetSymbolAddress((void**)&p_q_att, g_q_att_h);
    cudaGetSymbolAddress((void**)&p_wexp, g_wexp_h);
    cudaGetSymbolAddress((void**)&p_ctx, g_context_h);

    const int SMEM01 = STG * (ASZ + B0SZ) * 2;
    const int SMEM1  = STG * (ASZ + B1SZ) * 2;
    cudaFuncSetAttribute(hgemm<0>, cudaFuncAttributeMaxDynamicSharedMemorySize, SMEM01);
    cudaFuncSetAttribute(hgemm<1>, cudaFuncAttributeMaxDynamicSharedMemorySize, SMEM1);
    cudaFuncSetAttribute(hgemm<2>, cudaFuncAttributeMaxDynamicSharedMemorySize, SMEM01);
    cudaFuncSetAttribute(score_kernel, cudaFuncAttributeMaxDynamicSharedMemorySize, SCORE_SMEM);

    const size_t OUT1 = (size_t)S_ * B_ * H_;
    const size_t WSZ  = (size_t)S_ * S_ * B_;
    bool hasW = ((size_t)out_size >= OUT1 + WSZ);

    // 0. convert inputs to fp16
    f2h_kernel<<<8192, 256>>>(outs, p_outs_h, (int)(OUT1 / 8));
    f2h_kernel<<<8192, 256>>>(emb, p_emb_h, (int)((size_t)S_ * B_ * E_ / 8));
    f2h_kernel<<<64, 256>>>(W_enc, p_Wenc, A_ * E_ / 8);
    f2h_kernel<<<64, 256>>>(W_dec, p_Wdec, A_ * H_ / 8);
    f2h_kernel<<<128, 256>>>(W_h2h, p_Wh2h, H_ * H_ / 8);
    f2h_kernel<<<128, 256>>>(W_e2h, p_We2h, H_ * E_ / 8);

    // 1. zero wexp
    zero_wexp_kernel<<<(int)(WSZ * 2 / 16 / 256), 256>>>();

    // 2. projections: emb_att, q_att (half out)
    hgemm<0><<<dim3((S_ * B_) / BM, A_ / BN), 256, SMEM01>>>(
        p_emb_h, p_Wenc, nullptr, nullptr, b_enc, nullptr, p_emb_att, S_ * B_, A_, E_, 0);
    hgemm<0><<<dim3((S_ * B_) / BM, A_ / BN), 256, SMEM01>>>(
        p_outs_h, p_Wdec, nullptr, nullptr, b_dec, nullptr, p_q_att, S_ * B_, A_, H_, 1);

    // 3. scores + exp + rowsums
    score_kernel<<<dim3(S_ / SQ, B_), 256, SCORE_SMEM>>>(v);

    // 4. normalized weights output (q,k,b)
    if (hasW)
        norm_transpose_kernel<<<dim3(S_ / 32, S_), 256>>>(out + OUT1);

    // 5. context (triangular K, fused 1/rowsum, half out)
    hgemm<1><<<dim3(S_ / BM, E_ / BN, B_), 256, SMEM1>>>(
        p_wexp, p_emb_h, nullptr, nullptr, nullptr, nullptr, p_ctx, S_, E_, S_, 0);

    // 6. output = outs@W_h2h^T + ctx@W_e2h^T + b_h2h + b_e2h (fused dual-K)
    hgemm<2><<<dim3((S_ * B_) / BM, H_ / BN), 256, SMEM01>>>(
        p_outs_h, p_Wh2h, p_ctx, p_We2h, b_h2h, b_e2h, out, S_ * B_, H_, 1024, 0);
}